// round 13
// baseline (speedup 1.0000x reference)
#include <cuda_runtime.h>
#include <math.h>

#define BATCH 2
#define SEQ 2048
#define EMBED 1024
#define NHEAD 16
#define HDIM 64
#define BH (BATCH*NHEAD)       // 32
#define TOKENS (BATCH*SEQ)     // 4096

// Scratch (allocation-free rule: __device__ globals, zero-initialized).
// CRITICAL: these are referenced ONLY inside device code. Passing them as
// kernel arguments from host passes the host-shadow address, which on GB300
// (ATS/HMM) is silently writable host memory -> silent wrong answers.
__device__ float g_q[(size_t)BH * SEQ * HDIM];
__device__ float g_k[(size_t)BH * SEQ * HDIM];
__device__ float g_v[(size_t)BH * SEQ * HDIM];
__device__ float g_att[(size_t)TOKENS * EMBED];   // head-merged attention output

// ---------------------------------------------------------------------------
// Kernel 1: per-head projection for ONE tensor.  x:(B,S,E) -> out:(B,H,S,D),
// y = x_head @ W.T.  grid.x = 2048 (32 (token,head) rows per block), 256 thr.
// `which` selects the device-global destination (0=q, 1=k, 2=v).
// ---------------------------------------------------------------------------
__global__ __launch_bounds__(256) void proj_kernel(
    const float* __restrict__ x, const float* __restrict__ W, int which)
{
    __shared__ float Wt[64][64];   // Wt[j][i] = W[i][j]

    float* out = (which == 0) ? g_q : (which == 1) ? g_k : g_v;

    const int tid = threadIdx.x;

    // W: 4096 floats = 1024 float4; transpose into Wt
    for (int e = tid; e < 1024; e += 256) {
        float4 w4 = ((const float4*)W)[e];
        int i = e >> 4, j = (e & 15) * 4;
        Wt[j + 0][i] = w4.x;
        Wt[j + 1][i] = w4.y;
        Wt[j + 2][i] = w4.z;
        Wt[j + 3][i] = w4.w;
    }
    __syncthreads();

    const int rr = tid >> 3;                  // 0..31: row within block
    const int i0 = (tid & 7) * 8;             // 8 consecutive output dims
    const int r  = blockIdx.x * 32 + rr;      // (token, head) pair: r = t*16 + h
    const int t  = r >> 4, h = r & 15;

    const float4* xrow = (const float4*)(x + (size_t)t * EMBED + h * 64);

    float acc[8];
    #pragma unroll
    for (int ii = 0; ii < 8; ii++) acc[ii] = 0.f;

    #pragma unroll
    for (int j4 = 0; j4 < 16; j4++) {
        float4 x4 = xrow[j4];
        int j = j4 * 4;
        #pragma unroll
        for (int ii = 0; ii < 8; ii++) {
            acc[ii] += x4.x * Wt[j + 0][i0 + ii];
            acc[ii] += x4.y * Wt[j + 1][i0 + ii];
            acc[ii] += x4.z * Wt[j + 2][i0 + ii];
            acc[ii] += x4.w * Wt[j + 3][i0 + ii];
        }
    }

    const int b = t >> 11, s = t & 2047;      // SEQ = 2048
    float* orow = out + (((size_t)(b * NHEAD + h) * SEQ + s) * HDIM + i0);
    #pragma unroll
    for (int ii = 0; ii < 8; ii++) orow[ii] = acc[ii];
}

// ---------------------------------------------------------------------------
// XOR swizzle in float4-index space: bank-group (idx mod 8) XOR bits 7..9.
// Bijective within any 1024- or 512-float4 buffer.
// ---------------------------------------------------------------------------
__device__ __forceinline__ unsigned swz(unsigned i) { return i ^ ((i >> 7) & 7u); }

// ---------------------------------------------------------------------------
// Kernel 2: flash attention, fp32.  BM=64 q-rows, BN=32 keys/tile, D=64.
// grid: (SEQ/64, BH), block: (8,16) = 128 threads.
// Reads g_q/g_k/g_v, writes g_att — all device-global references in device code.
// smem: qs 16KB + ks 8KB (K tile, reused for P) + vs 8KB = 32KB static.
// ---------------------------------------------------------------------------
__global__ __launch_bounds__(128) void attn_kernel()
{
    __shared__ float4 qs[1024];   // 64 rows x 16 f4 (swizzled)
    __shared__ float4 ks[512];    // 32 rows x 16 f4 (swizzled); P: 64 rows x 8 f4
    __shared__ float4 vs[512];    // 32 rows x 16 f4 (plain)

    const int bh = blockIdx.y;
    const int b  = bh >> 4;
    const int h  = bh & 15;
    const size_t base = (size_t)bh * SEQ * HDIM;
    const float4* Q = (const float4*)(g_q + base);
    const float4* K = (const float4*)(g_k + base);
    const float4* V = (const float4*)(g_v + base);

    const int tx = threadIdx.x, ty = threadIdx.y;
    const int tid = ty * 8 + tx;
    const int q0 = blockIdx.x * 64;

    // load Q tile (LDG.128), pre-scaled by 1/sqrt(64) = 1/8
    {
        const float4* Qt = Q + q0 * (HDIM / 4);
        for (int e = tid; e < 1024; e += 128) {
            float4 q4 = Qt[e];
            q4.x *= 0.125f; q4.y *= 0.125f; q4.z *= 0.125f; q4.w *= 0.125f;
            qs[swz(e)] = q4;
        }
    }

    float m[4], l[4], o[4][8];
    #pragma unroll
    for (int r = 0; r < 4; r++) {
        m[r] = -1e30f; l[r] = 0.f;
        #pragma unroll
        for (int c = 0; c < 8; c++) o[r][c] = 0.f;
    }

    for (int kt = 0; kt < SEQ / 32; kt++) {
        __syncthreads();   // prev iter's P/V reads done (also covers Q load)
        const float4* Kt = K + kt * 32 * (HDIM / 4);
        const float4* Vt = V + kt * 32 * (HDIM / 4);
        for (int e = tid; e < 512; e += 128) {
            ks[swz(e)] = Kt[e];
            vs[e]      = Vt[e];
        }
        __syncthreads();

        // S = Q K^T (Q pre-scaled): 4 rows x 4 keys per thread
        float sc[4][4];
        #pragma unroll
        for (int r = 0; r < 4; r++)
            #pragma unroll
            for (int c = 0; c < 4; c++) sc[r][c] = 0.f;

        #pragma unroll 4
        for (int d4 = 0; d4 < 16; d4++) {
            float4 qv[4];
            #pragma unroll
            for (int r = 0; r < 4; r++)
                qv[r] = qs[swz((ty * 4 + r) * 16 + d4)];
            #pragma unroll
            for (int c = 0; c < 4; c++) {
                float4 kv = ks[swz((tx * 4 + c) * 16 + d4)];
                #pragma unroll
                for (int r = 0; r < 4; r++) {
                    sc[r][c] += qv[r].x * kv.x;
                    sc[r][c] += qv[r].y * kv.y;
                    sc[r][c] += qv[r].z * kv.z;
                    sc[r][c] += qv[r].w * kv.w;
                }
            }
        }

        // online softmax (row reduction across tx lanes: lane bits 0..2)
        float p[4][4];
        #pragma unroll
        for (int r = 0; r < 4; r++) {
            float rmax = sc[r][0];
            #pragma unroll
            for (int c = 1; c < 4; c++) rmax = fmaxf(rmax, sc[r][c]);
            rmax = fmaxf(rmax, __shfl_xor_sync(0xffffffffu, rmax, 1));
            rmax = fmaxf(rmax, __shfl_xor_sync(0xffffffffu, rmax, 2));
            rmax = fmaxf(rmax, __shfl_xor_sync(0xffffffffu, rmax, 4));
            float mnew = fmaxf(m[r], rmax);
            float corr = __expf(m[r] - mnew);
            float rsum = 0.f;
            #pragma unroll
            for (int c = 0; c < 4; c++) {
                p[r][c] = __expf(sc[r][c] - mnew);
                rsum += p[r][c];
            }
            rsum += __shfl_xor_sync(0xffffffffu, rsum, 1);
            rsum += __shfl_xor_sync(0xffffffffu, rsum, 2);
            rsum += __shfl_xor_sync(0xffffffffu, rsum, 4);
            l[r] = l[r] * corr + rsum;
            m[r] = mnew;
            #pragma unroll
            for (int c = 0; c < 8; c++) o[r][c] *= corr;
        }

        __syncthreads();           // all score-phase reads of ks done
        // stage P into ks: 64 rows x 8 f4, row=q-row, each f4 = 4 keys
        #pragma unroll
        for (int r = 0; r < 4; r++)
            ks[swz((ty * 4 + r) * 8 + tx)] =
                make_float4(p[r][0], p[r][1], p[r][2], p[r][3]);
        __syncthreads();

        // O += P @ V : key-chunks of 4
        #pragma unroll 2
        for (int k4 = 0; k4 < 8; k4++) {
            float4 pv[4];
            #pragma unroll
            for (int r = 0; r < 4; r++)
                pv[r] = ks[swz((ty * 4 + r) * 8 + k4)];
            #pragma unroll
            for (int kk = 0; kk < 4; kk++) {
                const int key = k4 * 4 + kk;
                float4 v0 = vs[key * 16 + tx * 2];
                float4 v1 = vs[key * 16 + tx * 2 + 1];
                float pr[4];
                #pragma unroll
                for (int r = 0; r < 4; r++)
                    pr[r] = (kk == 0) ? pv[r].x : (kk == 1) ? pv[r].y
                          : (kk == 2) ? pv[r].z : pv[r].w;
                #pragma unroll
                for (int r = 0; r < 4; r++) {
                    o[r][0] += pr[r] * v0.x;
                    o[r][1] += pr[r] * v0.y;
                    o[r][2] += pr[r] * v0.z;
                    o[r][3] += pr[r] * v0.w;
                    o[r][4] += pr[r] * v1.x;
                    o[r][5] += pr[r] * v1.y;
                    o[r][6] += pr[r] * v1.z;
                    o[r][7] += pr[r] * v1.w;
                }
            }
        }
    }

    // epilogue: normalize and write head-merged into g_att
    #pragma unroll
    for (int r = 0; r < 4; r++) {
        float inv = 1.0f / l[r];
        int srow = q0 + ty * 4 + r;
        float* orow = g_att + ((size_t)(b * SEQ + srow)) * EMBED + h * 64 + tx * 8;
        #pragma unroll
        for (int c = 0; c < 8; c++) orow[c] = o[r][c] * inv;
    }
}

// ---------------------------------------------------------------------------
// Kernel 3: output projection  out = g_att @ Wo^T + bo
// 64x64x16 tiles, 256 threads (16x16), 4x4 microtile.
// g_att read directly as device global; out is the harness's d_out.
// ---------------------------------------------------------------------------
__global__ __launch_bounds__(256) void outproj_kernel(
    const float* __restrict__ Wo, const float* __restrict__ bo,
    float* __restrict__ out)
{
    __shared__ float As[16][65];
    __shared__ float Bs[16][65];
    const int tx = threadIdx.x, ty = threadIdx.y;
    const int tid = ty * 16 + tx;
    const int rb = blockIdx.y * 64, cb = blockIdx.x * 64;

    float acc[4][4];
    #pragma unroll
    for (int i = 0; i < 4; i++)
        #pragma unroll
        for (int j = 0; j < 4; j++) acc[i][j] = 0.f;

    const int kk = tid & 15, mm = tid >> 4;

    for (int kb = 0; kb < EMBED; kb += 16) {
        #pragma unroll
        for (int p = 0; p < 4; p++) {
            As[kk][mm + 16 * p] = g_att[(size_t)(rb + mm + 16 * p) * EMBED + kb + kk];
            Bs[kk][mm + 16 * p] = Wo[(size_t)(cb + mm + 16 * p) * EMBED + kb + kk];
        }
        __syncthreads();
        #pragma unroll
        for (int k = 0; k < 16; k++) {
            float a[4], bb[4];
            #pragma unroll
            for (int i = 0; i < 4; i++) a[i]  = As[k][ty * 4 + i];
            #pragma unroll
            for (int j = 0; j < 4; j++) bb[j] = Bs[k][tx * 4 + j];
            #pragma unroll
            for (int i = 0; i < 4; i++)
                #pragma unroll
                for (int j = 0; j < 4; j++) acc[i][j] += a[i] * bb[j];
        }
        __syncthreads();
    }

    #pragma unroll
    for (int i = 0; i < 4; i++) {
        float* orow = out + (size_t)(rb + ty * 4 + i) * EMBED + cb + tx * 4;
        #pragma unroll
        for (int j = 0; j < 4; j++)
            orow[j] = acc[i][j] + bo[cb + tx * 4 + j];
    }
}

// ---------------------------------------------------------------------------
extern "C" void kernel_launch(void* const* d_in, const int* in_sizes, int n_in,
                              void* d_out, int out_size)
{
    // Robust input binding keyed on in_sizes (ground truth).
    const float *values, *keys, *queries, *Wv, *Wk, *Wq, *Wo, *bo;

    const int BIGN = TOKENS * EMBED;       // 4194304
    const int WN   = HDIM * HDIM;          // 4096
    const int WON  = EMBED * EMBED;        // 1048576
    const int BON  = EMBED;                // 1024

    if (n_in >= 8 &&
        in_sizes[0] == BIGN && in_sizes[1] == BIGN && in_sizes[2] == BIGN &&
        in_sizes[3] == WN   && in_sizes[4] == WN   && in_sizes[5] == WN &&
        in_sizes[6] == WON  && in_sizes[7] == BON) {
        // dict order: values, keys, queries, Wv, Wk, Wq, Wo, bo
        values  = (const float*)d_in[0];
        keys    = (const float*)d_in[1];
        queries = (const float*)d_in[2];
        Wv = (const float*)d_in[3];
        Wk = (const float*)d_in[4];
        Wq = (const float*)d_in[5];
        Wo = (const float*)d_in[6];
        bo = (const float*)d_in[7];
    } else if (n_in >= 8 &&
        in_sizes[0] == WN   && in_sizes[1] == WON  && in_sizes[2] == WN &&
        in_sizes[3] == WN   && in_sizes[4] == BON  &&
        in_sizes[5] == BIGN && in_sizes[6] == BIGN && in_sizes[7] == BIGN) {
        // alphabetical order: Wk, Wo, Wq, Wv, bo, keys, queries, values
        Wk = (const float*)d_in[0];
        Wo = (const float*)d_in[1];
        Wq = (const float*)d_in[2];
        Wv = (const float*)d_in[3];
        bo = (const float*)d_in[4];
        keys    = (const float*)d_in[5];
        queries = (const float*)d_in[6];
        values  = (const float*)d_in[7];
    } else {
        // generic fallback: classify by size, assume dict relative order
        const float* big[3]; int nbig = 0;
        const float* w64[3]; int nw = 0;
        Wo = 0; bo = 0;
        for (int i = 0; i < n_in; i++) {
            if (in_sizes[i] == BIGN && nbig < 3)      big[nbig++] = (const float*)d_in[i];
            else if (in_sizes[i] == WN && nw < 3)     w64[nw++]   = (const float*)d_in[i];
            else if (in_sizes[i] == WON)              Wo          = (const float*)d_in[i];
            else if (in_sizes[i] == BON)              bo          = (const float*)d_in[i];
        }
        values = big[0]; keys = big[1]; queries = big[2];
        Wv = w64[0]; Wk = w64[1]; Wq = w64[2];
    }

    float* out = (float*)d_out;
    (void)out_size;

    // 1) QKV projections — destinations selected inside device code
    const int pblocks = (TOKENS * NHEAD) / 32;    // 2048
    proj_kernel<<<pblocks, 256>>>(queries, Wq, 0);
    proj_kernel<<<pblocks, 256>>>(keys,    Wk, 1);
    proj_kernel<<<pblocks, 256>>>(values,  Wv, 2);

    // 2) flash attention — 32KB static smem, globals referenced in device code
    dim3 agrid(SEQ / 64, BH);
    attn_kernel<<<agrid, dim3(8, 16)>>>();

    // 3) output projection
    dim3 ggrid(EMBED / 64, TOKENS / 64);
    outproj_kernel<<<ggrid, dim3(16, 16)>>>(Wo, bo, out);
}

// round 17
// speedup vs baseline: 1.8305x; 1.8305x over previous
#include <cuda_runtime.h>
#include <math.h>

#define BATCH 2
#define SEQ 2048
#define EMBED 1024
#define NHEAD 16
#define HDIM 64
#define BH (BATCH*NHEAD)       // 32
#define TOKENS (BATCH*SEQ)     // 4096

// Scratch (allocation-free rule: __device__ globals, zero-initialized).
// CRITICAL: referenced ONLY inside device code (GB300 ATS makes host-shadow
// addresses silently writable host memory).
__device__ float g_q[(size_t)BH * SEQ * HDIM];
__device__ float g_k[(size_t)BH * SEQ * HDIM];
__device__ float g_v[(size_t)BH * SEQ * HDIM];
__device__ float g_att[(size_t)TOKENS * EMBED];   // head-merged attention output

// ---------------------------------------------------------------------------
// Kernel 1: per-head projection (outputs FULL fp32 — attn splits to tf32).
// ---------------------------------------------------------------------------
__global__ __launch_bounds__(256) void proj_kernel(
    const float* __restrict__ x, const float* __restrict__ W, int which)
{
    __shared__ float Wt[64][64];   // Wt[j][i] = W[i][j]

    float* out = (which == 0) ? g_q : (which == 1) ? g_k : g_v;

    const int tid = threadIdx.x;

    for (int e = tid; e < 1024; e += 256) {
        float4 w4 = ((const float4*)W)[e];
        int i = e >> 4, j = (e & 15) * 4;
        Wt[j + 0][i] = w4.x;
        Wt[j + 1][i] = w4.y;
        Wt[j + 2][i] = w4.z;
        Wt[j + 3][i] = w4.w;
    }
    __syncthreads();

    const int rr = tid >> 3;
    const int i0 = (tid & 7) * 8;
    const int r  = blockIdx.x * 32 + rr;      // r = t*16 + h
    const int t  = r >> 4, h = r & 15;

    const float4* xrow = (const float4*)(x + (size_t)t * EMBED + h * 64);

    float acc[8];
    #pragma unroll
    for (int ii = 0; ii < 8; ii++) acc[ii] = 0.f;

    #pragma unroll
    for (int j4 = 0; j4 < 16; j4++) {
        float4 x4 = xrow[j4];
        int j = j4 * 4;
        #pragma unroll
        for (int ii = 0; ii < 8; ii++) {
            acc[ii] += x4.x * Wt[j + 0][i0 + ii];
            acc[ii] += x4.y * Wt[j + 1][i0 + ii];
            acc[ii] += x4.z * Wt[j + 2][i0 + ii];
            acc[ii] += x4.w * Wt[j + 3][i0 + ii];
        }
    }

    const int b = t >> 11, s = t & 2047;
    float* orow = out + (((size_t)(b * NHEAD + h) * SEQ + s) * HDIM + i0);
    #pragma unroll
    for (int ii = 0; ii < 8; ii++) orow[ii] = acc[ii];
}

// ---------------------------------------------------------------------------
// tf32 helpers
// ---------------------------------------------------------------------------
__device__ __forceinline__ unsigned f2tf(float x) {
    unsigned u;
    asm("cvt.rna.tf32.f32 %0, %1;" : "=r"(u) : "f"(x));
    return u;
}
__device__ __forceinline__ float tf32f(float x) { return __uint_as_float(f2tf(x)); }

// mma.sync m16n8k8 tf32: D = A*B + D (fp32 accum)
__device__ __forceinline__ void mma8(float* c, const unsigned* a,
                                     unsigned b0, unsigned b1) {
    asm volatile(
        "mma.sync.aligned.m16n8k8.row.col.f32.tf32.tf32.f32 "
        "{%0,%1,%2,%3},{%4,%5,%6,%7},{%8,%9},{%0,%1,%2,%3};"
        : "+f"(c[0]), "+f"(c[1]), "+f"(c[2]), "+f"(c[3])
        : "r"(a[0]), "r"(a[1]), "r"(a[2]), "r"(a[3]), "r"(b0), "r"(b1));
}

// ---------------------------------------------------------------------------
// Kernel 2: flash attention, tf32 tensor cores. BM=64, BN=64, D=64.
// 128 threads = 4 warps, each warp owns 16 q-rows.
// Q*K^T uses 3xTF32 (hi/lo split) for precision; P*V straight tf32.
// smem strides chosen for conflict-free fragment LDS:
//   K stride 68 words -> b-load bank == lane (conflict-free)
//   V stride 72 words -> b-load conflict-free
//   P stride 68 words -> a-load conflict-free
// ---------------------------------------------------------------------------
#define KSTR 68
#define VSTR 72
#define PSTR 68
#define OFF_KHI 0
#define OFF_KLO (64*KSTR)                 // 4352
#define OFF_VS  (2*64*KSTR)               // 8704
#define OFF_PS  (2*64*KSTR + 64*VSTR)     // 13312
#define SMEMW   (OFF_PS + 64*PSTR)        // 17664 words = 70656 B

__global__ __launch_bounds__(128, 1) void attn_kernel()
{
    extern __shared__ float sm[];
    float* KHI = sm + OFF_KHI;
    float* KLO = sm + OFF_KLO;
    float* VS  = sm + OFF_VS;
    float* PS  = sm + OFF_PS;

    const int tid  = threadIdx.x;
    const int warp = tid >> 5, lane = tid & 31;
    const int g = lane >> 2, q4 = lane & 3;   // fragment group / thread-in-group
    const int bh = blockIdx.y, b = bh >> 4, h = bh & 15;
    const size_t base = (size_t)bh * SEQ * HDIM;
    const int q0 = blockIdx.x * 64;
    const int row0 = q0 + warp * 16;

    // ---- Q A-fragments, pre-scaled by 1/8, split hi/lo (held in regs) ----
    unsigned qhi[8][4], qlo[8][4];
    {
        const float* Qp = g_q + base;
        #pragma unroll
        for (int kc = 0; kc < 8; kc++) {
            int c0 = kc * 8 + q4;
            float v[4];
            v[0] = Qp[(size_t)(row0 + g    ) * HDIM + c0    ] * 0.125f;
            v[1] = Qp[(size_t)(row0 + g + 8) * HDIM + c0    ] * 0.125f;
            v[2] = Qp[(size_t)(row0 + g    ) * HDIM + c0 + 4] * 0.125f;
            v[3] = Qp[(size_t)(row0 + g + 8) * HDIM + c0 + 4] * 0.125f;
            #pragma unroll
            for (int i = 0; i < 4; i++) {
                qhi[kc][i] = f2tf(v[i]);
                qlo[kc][i] = f2tf(v[i] - __uint_as_float(qhi[kc][i]));
            }
        }
    }

    float S[8][4], O[8][4];
    #pragma unroll
    for (int nc = 0; nc < 8; nc++)
        #pragma unroll
        for (int i = 0; i < 4; i++) O[nc][i] = 0.f;
    float m0 = -1e30f, m1 = -1e30f, l0 = 0.f, l1 = 0.f;

    for (int kt = 0; kt < SEQ / 64; kt++) {
        __syncthreads();   // prev iter's K/V/P reads complete
        const float4* Kt = (const float4*)(g_k + base + (size_t)kt * 64 * HDIM);
        const float4* Vt = (const float4*)(g_v + base + (size_t)kt * 64 * HDIM);
        #pragma unroll
        for (int i = 0; i < 8; i++) {
            int e = tid + i * 128;          // e = key*16 + d4 (coalesced)
            int key = e >> 4, d4 = e & 15;
            float4 kv = Kt[e];
            float4 hi, lo;
            hi.x = tf32f(kv.x); lo.x = tf32f(kv.x - hi.x);
            hi.y = tf32f(kv.y); lo.y = tf32f(kv.y - hi.y);
            hi.z = tf32f(kv.z); lo.z = tf32f(kv.z - hi.z);
            hi.w = tf32f(kv.w); lo.w = tf32f(kv.w - hi.w);
            *(float4*)&KHI[key * KSTR + d4 * 4] = hi;
            *(float4*)&KLO[key * KSTR + d4 * 4] = lo;
            float4 vv = Vt[e];
            float4 vh;
            vh.x = tf32f(vv.x); vh.y = tf32f(vv.y);
            vh.z = tf32f(vv.z); vh.w = tf32f(vv.w);
            *(float4*)&VS[key * VSTR + d4 * 4] = vh;
        }
        __syncthreads();

        // ---- S = Q K^T, 3xTF32 ----
        #pragma unroll
        for (int nc = 0; nc < 8; nc++) {
            S[nc][0] = 0.f; S[nc][1] = 0.f; S[nc][2] = 0.f; S[nc][3] = 0.f;
        }
        #pragma unroll
        for (int kc = 0; kc < 8; kc++) {
            #pragma unroll
            for (int nc = 0; nc < 8; nc++) {
                int kb = (nc * 8 + g) * KSTR + kc * 8 + q4;  // b0: K[key][dim]
                unsigned bh0 = __float_as_uint(KHI[kb]);
                unsigned bh1 = __float_as_uint(KHI[kb + 4]);
                unsigned bl0 = __float_as_uint(KLO[kb]);
                unsigned bl1 = __float_as_uint(KLO[kb + 4]);
                mma8(S[nc], qhi[kc], bh0, bh1);
                mma8(S[nc], qlo[kc], bh0, bh1);
                mma8(S[nc], qhi[kc], bl0, bl1);
            }
        }

        // ---- online softmax (rows g and g+8; lanes 4g..4g+3 share a row) ----
        float mx0 = -1e30f, mx1 = -1e30f;
        #pragma unroll
        for (int nc = 0; nc < 8; nc++) {
            mx0 = fmaxf(mx0, fmaxf(S[nc][0], S[nc][1]));
            mx1 = fmaxf(mx1, fmaxf(S[nc][2], S[nc][3]));
        }
        mx0 = fmaxf(mx0, __shfl_xor_sync(0xffffffffu, mx0, 1));
        mx0 = fmaxf(mx0, __shfl_xor_sync(0xffffffffu, mx0, 2));
        mx1 = fmaxf(mx1, __shfl_xor_sync(0xffffffffu, mx1, 1));
        mx1 = fmaxf(mx1, __shfl_xor_sync(0xffffffffu, mx1, 2));
        float mn0 = fmaxf(m0, mx0), mn1 = fmaxf(m1, mx1);
        float c0 = __expf(m0 - mn0), c1 = __expf(m1 - mn1);
        float s0 = 0.f, s1 = 0.f;
        #pragma unroll
        for (int nc = 0; nc < 8; nc++) {
            S[nc][0] = __expf(S[nc][0] - mn0); s0 += S[nc][0];
            S[nc][1] = __expf(S[nc][1] - mn0); s0 += S[nc][1];
            S[nc][2] = __expf(S[nc][2] - mn1); s1 += S[nc][2];
            S[nc][3] = __expf(S[nc][3] - mn1); s1 += S[nc][3];
        }
        s0 += __shfl_xor_sync(0xffffffffu, s0, 1);
        s0 += __shfl_xor_sync(0xffffffffu, s0, 2);
        s1 += __shfl_xor_sync(0xffffffffu, s1, 1);
        s1 += __shfl_xor_sync(0xffffffffu, s1, 2);
        l0 = l0 * c0 + s0;  l1 = l1 * c1 + s1;
        m0 = mn0;           m1 = mn1;
        #pragma unroll
        for (int nc = 0; nc < 8; nc++) {
            O[nc][0] *= c0; O[nc][1] *= c0;
            O[nc][2] *= c1; O[nc][3] *= c1;
        }

        // ---- stage P (tf32) into per-warp smem slice ----
        #pragma unroll
        for (int nc = 0; nc < 8; nc++) {
            float2 p01 = make_float2(tf32f(S[nc][0]), tf32f(S[nc][1]));
            float2 p23 = make_float2(tf32f(S[nc][2]), tf32f(S[nc][3]));
            *(float2*)&PS[(warp * 16 + g    ) * PSTR + nc * 8 + 2 * q4] = p01;
            *(float2*)&PS[(warp * 16 + g + 8) * PSTR + nc * 8 + 2 * q4] = p23;
        }
        __syncwarp();

        // ---- O += P V ----
        #pragma unroll
        for (int kc = 0; kc < 8; kc++) {
            unsigned a[4];
            int pb = (warp * 16 + g) * PSTR + kc * 8 + q4;
            a[0] = __float_as_uint(PS[pb]);
            a[1] = __float_as_uint(PS[pb + 8 * PSTR]);
            a[2] = __float_as_uint(PS[pb + 4]);
            a[3] = __float_as_uint(PS[pb + 8 * PSTR + 4]);
            #pragma unroll
            for (int nc = 0; nc < 8; nc++) {
                int vb = (kc * 8 + q4) * VSTR + nc * 8 + g;  // b0: V[key][dim]
                unsigned b0 = __float_as_uint(VS[vb]);
                unsigned b1 = __float_as_uint(VS[vb + 4 * VSTR]);
                mma8(O[nc], a, b0, b1);
            }
        }
    }

    // ---- epilogue: normalize, write head-merged ----
    float i0 = 1.f / l0, i1 = 1.f / l1;
    int r0g = q0 + warp * 16 + g;
    #pragma unroll
    for (int nc = 0; nc < 8; nc++) {
        int col = h * 64 + nc * 8 + 2 * q4;
        float2 o01 = make_float2(O[nc][0] * i0, O[nc][1] * i0);
        float2 o23 = make_float2(O[nc][2] * i1, O[nc][3] * i1);
        *(float2*)&g_att[(size_t)(b * SEQ + r0g    ) * EMBED + col] = o01;
        *(float2*)&g_att[(size_t)(b * SEQ + r0g + 8) * EMBED + col] = o23;
    }
}

// ---------------------------------------------------------------------------
// Kernel 3: output projection  out = g_att @ Wo^T + bo  (known-good FFMA,
// untouched — next target once attn tf32 is confirmed)
// ---------------------------------------------------------------------------
__global__ __launch_bounds__(256) void outproj_kernel(
    const float* __restrict__ Wo, const float* __restrict__ bo,
    float* __restrict__ out)
{
    __shared__ float As[16][65];
    __shared__ float Bs[16][65];
    const int tx = threadIdx.x, ty = threadIdx.y;
    const int tid = ty * 16 + tx;
    const int rb = blockIdx.y * 64, cb = blockIdx.x * 64;

    float acc[4][4];
    #pragma unroll
    for (int i = 0; i < 4; i++)
        #pragma unroll
        for (int j = 0; j < 4; j++) acc[i][j] = 0.f;

    const int kk = tid & 15, mm = tid >> 4;

    for (int kb = 0; kb < EMBED; kb += 16) {
        #pragma unroll
        for (int p = 0; p < 4; p++) {
            As[kk][mm + 16 * p] = g_att[(size_t)(rb + mm + 16 * p) * EMBED + kb + kk];
            Bs[kk][mm + 16 * p] = Wo[(size_t)(cb + mm + 16 * p) * EMBED + kb + kk];
        }
        __syncthreads();
        #pragma unroll
        for (int k = 0; k < 16; k++) {
            float a[4], bb[4];
            #pragma unroll
            for (int i = 0; i < 4; i++) a[i]  = As[k][ty * 4 + i];
            #pragma unroll
            for (int j = 0; j < 4; j++) bb[j] = Bs[k][tx * 4 + j];
            #pragma unroll
            for (int i = 0; i < 4; i++)
                #pragma unroll
                for (int j = 0; j < 4; j++) acc[i][j] += a[i] * bb[j];
        }
        __syncthreads();
    }

    #pragma unroll
    for (int i = 0; i < 4; i++) {
        float* orow = out + (size_t)(rb + ty * 4 + i) * EMBED + cb + tx * 4;
        #pragma unroll
        for (int j = 0; j < 4; j++)
            orow[j] = acc[i][j] + bo[cb + tx * 4 + j];
    }
}

// ---------------------------------------------------------------------------
extern "C" void kernel_launch(void* const* d_in, const int* in_sizes, int n_in,
                              void* d_out, int out_size)
{
    const float *values, *keys, *queries, *Wv, *Wk, *Wq, *Wo, *bo;

    const int BIGN = TOKENS * EMBED;       // 4194304
    const int WN   = HDIM * HDIM;          // 4096
    const int WON  = EMBED * EMBED;        // 1048576
    const int BON  = EMBED;                // 1024

    if (n_in >= 8 &&
        in_sizes[0] == BIGN && in_sizes[1] == BIGN && in_sizes[2] == BIGN &&
        in_sizes[3] == WN   && in_sizes[4] == WN   && in_sizes[5] == WN &&
        in_sizes[6] == WON  && in_sizes[7] == BON) {
        values  = (const float*)d_in[0];
        keys    = (const float*)d_in[1];
        queries = (const float*)d_in[2];
        Wv = (const float*)d_in[3];
        Wk = (const float*)d_in[4];
        Wq = (const float*)d_in[5];
        Wo = (const float*)d_in[6];
        bo = (const float*)d_in[7];
    } else if (n_in >= 8 &&
        in_sizes[0] == WN   && in_sizes[1] == WON  && in_sizes[2] == WN &&
        in_sizes[3] == WN   && in_sizes[4] == BON  &&
        in_sizes[5] == BIGN && in_sizes[6] == BIGN && in_sizes[7] == BIGN) {
        Wk = (const float*)d_in[0];
        Wo = (const float*)d_in[1];
        Wq = (const float*)d_in[2];
        Wv = (const float*)d_in[3];
        bo = (const float*)d_in[4];
        keys    = (const float*)d_in[5];
        queries = (const float*)d_in[6];
        values  = (const float*)d_in[7];
    } else {
        const float* big[3]; int nbig = 0;
        const float* w64[3]; int nw = 0;
        Wo = 0; bo = 0;
        for (int i = 0; i < n_in; i++) {
            if (in_sizes[i] == BIGN && nbig < 3)      big[nbig++] = (const float*)d_in[i];
            else if (in_sizes[i] == WN && nw < 3)     w64[nw++]   = (const float*)d_in[i];
            else if (in_sizes[i] == WON)              Wo          = (const float*)d_in[i];
            else if (in_sizes[i] == BON)              bo          = (const float*)d_in[i];
        }
        values = big[0]; keys = big[1]; queries = big[2];
        Wv = w64[0]; Wk = w64[1]; Wq = w64[2];
    }

    float* out = (float*)d_out;
    (void)out_size;

    // 1) QKV projections
    const int pblocks = (TOKENS * NHEAD) / 32;    // 2048
    proj_kernel<<<pblocks, 256>>>(queries, Wq, 0);
    proj_kernel<<<pblocks, 256>>>(keys,    Wk, 1);
    proj_kernel<<<pblocks, 256>>>(values,  Wv, 2);

    // 2) flash attention (tf32 tensor cores), 70656 B dynamic smem
    const int attn_smem = SMEMW * (int)sizeof(float);
    cudaFuncSetAttribute(attn_kernel, cudaFuncAttributeMaxDynamicSharedMemorySize,
                         attn_smem);
    dim3 agrid(SEQ / 64, BH);
    attn_kernel<<<agrid, 128, attn_smem>>>();

    // 3) output projection
    dim3 ggrid(EMBED / 64, TOKENS / 64);
    outproj_kernel<<<ggrid, dim3(16, 16)>>>(Wo, bo, out);
}